// round 6
// baseline (speedup 1.0000x reference)
#include <cuda_runtime.h>
#include <cuda_bf16.h>
#include <math.h>

// Problem-fixed capacities
#define NMAX 50000
#define EMAX 800000

// ---------------- scratch (no allocation allowed) ----------------
__device__ int   g_is64;
__device__ int   g_deg[NMAX];
__device__ int   g_cursor[NMAX];
__device__ float g_dinv[NMAX];
__device__ int   g_rowptr[NMAX + 1];
__device__ int   g_col[EMAX];
__device__ float g_w[EMAX];
__device__ __align__(256) float g_bufA[NMAX * 128];
__device__ __align__(256) float g_bufB[NMAX * 128];

// packed dual-fp32 FMA (FFMA2) — PTX-only on sm_103a
__device__ __forceinline__ unsigned long long ffma2(unsigned long long a,
                                                    unsigned long long b,
                                                    unsigned long long c) {
    unsigned long long d;
    asm("fma.rn.f32x2 %0, %1, %2, %3;" : "=l"(d) : "l"(a), "l"(b), "l"(c));
    return d;
}

// Edge index accessor: handles int32 (JAX x64-disabled) and int64 layouts.
__device__ __forceinline__ int edge_at(const void* ei, long idx) {
    if (g_is64) return (int)((const long long*)ei)[idx];
    return ((const int*)ei)[idx];
}

// ---------------- dtype detection (parallel) ----------------
__global__ void k_detect(const void* ei, int e) {
    const long long* p = (const long long*)ei;
    int m = e < 2048 ? e : 2048;
    int ok = 1;
    for (int i = threadIdx.x; i < m; i += blockDim.x) {
        long long v = p[i];
        if (v < 0 || v >= NMAX) ok = 0;
    }
    int all = __syncthreads_and(ok);
    if (threadIdx.x == 0) g_is64 = all;
}

// ---------------- degree count ----------------
__global__ void k_count(const void* __restrict__ ei, int e) {
    int i = blockIdx.x * blockDim.x + threadIdx.x;
    if (i < e) {
        int d = edge_at(ei, (long)e + i);  // dst row
        if (d >= 0 && d < NMAX) atomicAdd(&g_deg[d], 1);
    }
}

// ---------------- single-block exclusive scan + dinv ----------------
__global__ void k_scan(int n, int e_total) {
    __shared__ int warp_pref[32];
    __shared__ int s_carry;
    int tid = threadIdx.x, lane = tid & 31, wid = tid >> 5;
    if (tid == 0) s_carry = 0;
    __syncthreads();
    for (int base = 0; base < n; base += 1024) {
        int i = base + tid;
        int v = (i < n) ? g_deg[i] : 0;
        if (i < n) g_dinv[i] = rsqrtf((float)(v + 1));  // +1 self loop
        int incl = v;
        #pragma unroll
        for (int off = 1; off < 32; off <<= 1) {
            int t = __shfl_up_sync(0xffffffffu, incl, off);
            if (lane >= off) incl += t;
        }
        if (lane == 31) warp_pref[wid] = incl;
        __syncthreads();
        if (wid == 0) {
            int ws = warp_pref[lane];
            int wincl = ws;
            #pragma unroll
            for (int off = 1; off < 32; off <<= 1) {
                int t = __shfl_up_sync(0xffffffffu, wincl, off);
                if (lane >= off) wincl += t;
            }
            warp_pref[lane] = wincl - ws;  // exclusive warp prefix
        }
        __syncthreads();
        int excl = s_carry + warp_pref[wid] + incl - v;
        if (i < n) { g_rowptr[i] = excl; g_cursor[i] = excl; }
        __syncthreads();
        if (tid == 1023) s_carry = s_carry + warp_pref[31] + incl;
        __syncthreads();
    }
    if (threadIdx.x == 0) g_rowptr[n] = e_total;
}

// ---------------- CSR fill ----------------
__global__ void k_fill(const void* __restrict__ ei, int e) {
    int i = blockIdx.x * blockDim.x + threadIdx.x;
    if (i < e) {
        int s = edge_at(ei, i);
        int d = edge_at(ei, (long)e + i);
        if (s >= 0 && s < NMAX && d >= 0 && d < NMAX) {
            int pos = atomicAdd(&g_cursor[d], 1);
            if (pos >= 0 && pos < EMAX) {
                g_col[pos] = s;
                g_w[pos]   = g_dinv[s];
            }
        }
    }
}

// ---------------- fp32 GEMM with FFMA2: C[M,ND] = A[M,KD] @ B[KD,ND] ----------------
// 128x64 CTA tile, BK=16, 8x4 per-thread as 4 m-pairs x 4 n, f32x2 packed FMAs.
template<int KD, int ND>
__global__ void __launch_bounds__(256) k_gemm(const float* __restrict__ A,
                                              const float* __restrict__ B,
                                              float* __restrict__ C, int M) {
    const int BM = 128, BN = 64, BK = 16;
    __shared__ float  As[BK][BM + 4];
    __shared__ float2 Bs2[BK][BN];      // duplicated (b,b) pairs
    int bm = blockIdx.x * BM;
    int bn = blockIdx.y * BN;
    int tid = threadIdx.x;
    int tm = (tid >> 4) << 3;   // 0..120 (8 m = 4 pairs)
    int tn = (tid & 15) << 2;   // 0..60  (4 n)
    unsigned long long acc[4][4] = {};  // [m-pair][n], each = (m even, m odd)

    for (int k0 = 0; k0 < KD; k0 += BK) {
        // Load A tile: 512 float4s, transpose into As[kk][m]
        #pragma unroll
        for (int f = tid; f < 512; f += 256) {
            int ml = f >> 2, c = f & 3;
            int gm = bm + ml;
            float4 v = (gm < M) ? *(const float4*)&A[(long)gm * KD + k0 + 4 * c]
                                : make_float4(0.f, 0.f, 0.f, 0.f);
            As[4 * c + 0][ml] = v.x;
            As[4 * c + 1][ml] = v.y;
            As[4 * c + 2][ml] = v.z;
            As[4 * c + 3][ml] = v.w;
        }
        // Load B tile duplicated: each thread one float4 -> two dup float4s
        {
            int kk = tid >> 4;
            int nn = (tid & 15) << 2;
            float4 b = *(const float4*)&B[(long)(k0 + kk) * ND + bn + nn];
            *(float4*)&Bs2[kk][nn]     = make_float4(b.x, b.x, b.y, b.y);
            *(float4*)&Bs2[kk][nn + 2] = make_float4(b.z, b.z, b.w, b.w);
        }
        __syncthreads();
        #pragma unroll
        for (int kk = 0; kk < BK; kk++) {
            ulonglong2 aA = *(const ulonglong2*)&As[kk][tm];       // pairs (m0,m1),(m2,m3)
            ulonglong2 aB = *(const ulonglong2*)&As[kk][tm + 4];   // pairs (m4,m5),(m6,m7)
            ulonglong2 bA = *(const ulonglong2*)&Bs2[kk][tn];      // dup(n0), dup(n1)
            ulonglong2 bB = *(const ulonglong2*)&Bs2[kk][tn + 2];  // dup(n2), dup(n3)
            acc[0][0] = ffma2(aA.x, bA.x, acc[0][0]);
            acc[0][1] = ffma2(aA.x, bA.y, acc[0][1]);
            acc[0][2] = ffma2(aA.x, bB.x, acc[0][2]);
            acc[0][3] = ffma2(aA.x, bB.y, acc[0][3]);
            acc[1][0] = ffma2(aA.y, bA.x, acc[1][0]);
            acc[1][1] = ffma2(aA.y, bA.y, acc[1][1]);
            acc[1][2] = ffma2(aA.y, bB.x, acc[1][2]);
            acc[1][3] = ffma2(aA.y, bB.y, acc[1][3]);
            acc[2][0] = ffma2(aB.x, bA.x, acc[2][0]);
            acc[2][1] = ffma2(aB.x, bA.y, acc[2][1]);
            acc[2][2] = ffma2(aB.x, bB.x, acc[2][2]);
            acc[2][3] = ffma2(aB.x, bB.y, acc[2][3]);
            acc[3][0] = ffma2(aB.y, bA.x, acc[3][0]);
            acc[3][1] = ffma2(aB.y, bA.y, acc[3][1]);
            acc[3][2] = ffma2(aB.y, bB.x, acc[3][2]);
            acc[3][3] = ffma2(aB.y, bB.y, acc[3][3]);
        }
        __syncthreads();
    }
    // Epilogue: unpack pairs, write two rows per m-pair
    #pragma unroll
    for (int i = 0; i < 4; i++) {
        float2 c0 = *(float2*)&acc[i][0];
        float2 c1 = *(float2*)&acc[i][1];
        float2 c2 = *(float2*)&acc[i][2];
        float2 c3 = *(float2*)&acc[i][3];
        int gm0 = bm + tm + 2 * i;
        if (gm0 < M)
            *(float4*)&C[(long)gm0 * ND + bn + tn] = make_float4(c0.x, c1.x, c2.x, c3.x);
        if (gm0 + 1 < M)
            *(float4*)&C[(long)(gm0 + 1) * ND + bn + tn] = make_float4(c0.y, c1.y, c2.y, c3.y);
    }
}

// ---------------- gather aggregation + bias + tanh (F=128) ----------------
__global__ void __launch_bounds__(256) k_agg128(const float* __restrict__ h,
                                                const float* __restrict__ bias,
                                                float* __restrict__ out, int n) {
    int node = blockIdx.x * 8 + (threadIdx.x >> 5);
    if (node >= n) return;
    int lane = threadIdx.x & 31;
    const float4* hv = (const float4*)h;
    float di = g_dinv[node];
    float4 a = __ldg(&hv[(long)node * 32 + lane]);
    float4 acc;
    acc.x = di * a.x; acc.y = di * a.y; acc.z = di * a.z; acc.w = di * a.w;
    int beg = g_rowptr[node], end = g_rowptr[node + 1];
    #pragma unroll 4
    for (int p = beg; p < end; p++) {
        int s = g_col[p];
        float ws = g_w[p];
        float4 v = __ldg(&hv[(long)s * 32 + lane]);
        acc.x += ws * v.x; acc.y += ws * v.y; acc.z += ws * v.z; acc.w += ws * v.w;
    }
    float4 b = __ldg(&((const float4*)bias)[lane]);
    float4 r;
    r.x = tanhf(di * acc.x + b.x);
    r.y = tanhf(di * acc.y + b.y);
    r.z = tanhf(di * acc.z + b.z);
    r.w = tanhf(di * acc.w + b.w);
    ((float4*)out)[(long)node * 32 + lane] = r;
}

// ---------------- gather aggregation + bias + tanh (F=64) ----------------
__global__ void __launch_bounds__(256) k_agg64(const float* __restrict__ h,
                                               const float* __restrict__ bias,
                                               float* __restrict__ out, int n) {
    int node = blockIdx.x * 8 + (threadIdx.x >> 5);
    if (node >= n) return;
    int lane = threadIdx.x & 31;
    const float2* hv = (const float2*)h;
    float di = g_dinv[node];
    float2 a = __ldg(&hv[(long)node * 32 + lane]);
    float2 acc;
    acc.x = di * a.x; acc.y = di * a.y;
    int beg = g_rowptr[node], end = g_rowptr[node + 1];
    #pragma unroll 4
    for (int p = beg; p < end; p++) {
        int s = g_col[p];
        float ws = g_w[p];
        float2 v = __ldg(&hv[(long)s * 32 + lane]);
        acc.x += ws * v.x; acc.y += ws * v.y;
    }
    float2 b = __ldg(&((const float2*)bias)[lane]);
    float2 r;
    r.x = tanhf(di * acc.x + b.x);
    r.y = tanhf(di * acc.y + b.y);
    ((float2*)out)[(long)node * 32 + lane] = r;
}

// ---------------- fused MLP head: tanh(h@Wf1+bf1)@Wf2+bf2 ----------------
__global__ void __launch_bounds__(256) k_mlp(const float* __restrict__ h,
                                             const float* __restrict__ Wf1,
                                             const float* __restrict__ bf1,
                                             const float* __restrict__ Wf2,
                                             const float* __restrict__ bf2,
                                             float* __restrict__ out, int n) {
    __shared__ float sW[64 * 32];
    __shared__ float sb1[32];
    __shared__ float sW2[32];
    __shared__ float sb2;
    for (int i = threadIdx.x; i < 64 * 32; i += blockDim.x) sW[i] = Wf1[i];
    if (threadIdx.x < 32) { sb1[threadIdx.x] = bf1[threadIdx.x]; sW2[threadIdx.x] = Wf2[threadIdx.x]; }
    if (threadIdx.x == 0) sb2 = bf2[0];
    __syncthreads();

    int node = blockIdx.x * 8 + (threadIdx.x >> 5);
    if (node >= n) return;
    int lane = threadIdx.x & 31;
    const float* row = h + (long)node * 64;
    float acc = sb1[lane];
    #pragma unroll
    for (int j = 0; j < 64; j++)
        acc += __ldg(&row[j]) * sW[j * 32 + lane];
    float t = tanhf(acc);
    float y = t * sW2[lane];
    #pragma unroll
    for (int off = 16; off; off >>= 1)
        y += __shfl_down_sync(0xffffffffu, y, off);
    if (lane == 0) out[node] = y + sb2;
}

// ---------------- launch ----------------
extern "C" void kernel_launch(void* const* d_in, const int* in_sizes, int n_in,
                              void* d_out, int out_size) {
    const float* x   = (const float*)d_in[0];
    const void*  ei  = d_in[1];
    const float* W1  = (const float*)d_in[2];
    const float* b1  = (const float*)d_in[3];
    const float* W2  = (const float*)d_in[4];
    const float* b2  = (const float*)d_in[5];
    const float* Wf1 = (const float*)d_in[6];
    const float* bf1 = (const float*)d_in[7];
    const float* Wf2 = (const float*)d_in[8];
    const float* bf2 = (const float*)d_in[9];
    float* out = (float*)d_out;

    int n = in_sizes[0] / 128;   // 50000
    int e = in_sizes[1] / 2;     // 800000

    float* bufA; cudaGetSymbolAddress((void**)&bufA, g_bufA);
    float* bufB; cudaGetSymbolAddress((void**)&bufB, g_bufB);
    int*   degp; cudaGetSymbolAddress((void**)&degp, g_deg);

    int ge = (e + 255) / 256;
    int gw = (n + 7) / 8;        // warp-per-node kernels

    // CSR build
    k_detect<<<1, 1024>>>(ei, e);
    cudaMemsetAsync(degp, 0, (size_t)n * sizeof(int));
    k_count<<<ge, 256>>>(ei, e);
    k_scan<<<1, 1024>>>(n, e);
    k_fill<<<ge, 256>>>(ei, e);

    // Layer 1: h1 = tanh(Agg(x@W1) + b1)   [n,128]
    {
        dim3 grid((n + 127) / 128, 2);
        k_gemm<128, 128><<<grid, 256>>>(x, W1, bufA, n);
    }
    k_agg128<<<gw, 256>>>(bufA, b1, bufB, n);

    // Layer 2: h2 = tanh(Agg(h1@W2) + b2)  [n,64]
    {
        dim3 grid((n + 127) / 128, 1);
        k_gemm<128, 64><<<grid, 256>>>(bufB, W2, bufA, n);
    }
    k_agg64<<<gw, 256>>>(bufA, b2, bufB, n);

    // Head: out = tanh(h2@Wf1+bf1)@Wf2+bf2  [n,1]
    k_mlp<<<gw, 256>>>(bufB, Wf1, bf1, Wf2, bf2, out, n);
}

// round 7
// speedup vs baseline: 1.2795x; 1.2795x over previous
#include <cuda_runtime.h>
#include <cuda_bf16.h>
#include <math.h>

// Problem-fixed capacities
#define NMAX 50000
#define EMAX 800000

// ---------------- scratch (no allocation allowed) ----------------
__device__ int   g_is64;
__device__ int   g_deg[NMAX];
__device__ int   g_cursor[NMAX];
__device__ float g_dinv[NMAX];
__device__ int   g_rowptr[NMAX + 1];
__device__ int   g_col[EMAX];
__device__ __align__(256) float g_bufA[NMAX * 128];
__device__ __align__(256) float g_bufB[NMAX * 128];

// Edge index accessor: handles int32 (JAX x64-disabled) and int64 layouts.
__device__ __forceinline__ int edge_at(const void* ei, long idx) {
    if (g_is64) return (int)((const long long*)ei)[idx];
    return ((const int*)ei)[idx];
}

// ---------------- dtype detection (parallel) ----------------
__global__ void k_detect(const void* ei, int e) {
    const long long* p = (const long long*)ei;
    int m = e < 2048 ? e : 2048;
    int ok = 1;
    for (int i = threadIdx.x; i < m; i += blockDim.x) {
        long long v = p[i];
        if (v < 0 || v >= NMAX) ok = 0;
    }
    int all = __syncthreads_and(ok);
    if (threadIdx.x == 0) g_is64 = all;
}

// ---------------- degree count ----------------
__global__ void k_count(const void* __restrict__ ei, int e) {
    int i = blockIdx.x * blockDim.x + threadIdx.x;
    if (i < e) {
        int d = edge_at(ei, (long)e + i);  // dst row
        if (d >= 0 && d < NMAX) atomicAdd(&g_deg[d], 1);
    }
}

// ---------------- single-block exclusive scan + dinv ----------------
__global__ void k_scan(int n, int e_total) {
    __shared__ int warp_pref[32];
    __shared__ int s_carry;
    int tid = threadIdx.x, lane = tid & 31, wid = tid >> 5;
    if (tid == 0) s_carry = 0;
    __syncthreads();
    for (int base = 0; base < n; base += 1024) {
        int i = base + tid;
        int v = (i < n) ? g_deg[i] : 0;
        if (i < n) g_dinv[i] = rsqrtf((float)(v + 1));  // +1 self loop
        int incl = v;
        #pragma unroll
        for (int off = 1; off < 32; off <<= 1) {
            int t = __shfl_up_sync(0xffffffffu, incl, off);
            if (lane >= off) incl += t;
        }
        if (lane == 31) warp_pref[wid] = incl;
        __syncthreads();
        if (wid == 0) {
            int ws = warp_pref[lane];
            int wincl = ws;
            #pragma unroll
            for (int off = 1; off < 32; off <<= 1) {
                int t = __shfl_up_sync(0xffffffffu, wincl, off);
                if (lane >= off) wincl += t;
            }
            warp_pref[lane] = wincl - ws;  // exclusive warp prefix
        }
        __syncthreads();
        int excl = s_carry + warp_pref[wid] + incl - v;
        if (i < n) { g_rowptr[i] = excl; g_cursor[i] = excl; }
        __syncthreads();
        if (tid == 1023) s_carry = s_carry + warp_pref[31] + incl;
        __syncthreads();
    }
    if (threadIdx.x == 0) g_rowptr[n] = e_total;
}

// ---------------- CSR fill (col only — weights folded into GEMM epilogue) ----------------
__global__ void k_fill(const void* __restrict__ ei, int e) {
    int i = blockIdx.x * blockDim.x + threadIdx.x;
    if (i < e) {
        int s = edge_at(ei, i);
        int d = edge_at(ei, (long)e + i);
        if (s >= 0 && s < NMAX && d >= 0 && d < NMAX) {
            int pos = atomicAdd(&g_cursor[d], 1);
            if (pos >= 0 && pos < EMAX) g_col[pos] = s;
        }
    }
}

// ---------------- fp32 GEMM + dinv row-scale: C[m,:] = dinv[m] * (A[m,:] @ B) ----------------
// 128x64 CTA tile, BK=16, 8x4 per-thread, all-LDS.128 inner loop.
template<int KD, int ND>
__global__ void __launch_bounds__(256) k_gemm(const float* __restrict__ A,
                                              const float* __restrict__ B,
                                              float* __restrict__ C, int M) {
    const int BM = 128, BN = 64, BK = 16;
    __shared__ float As[BK][BM + 4];
    __shared__ float Bs[BK][BN];
    int bm = blockIdx.x * BM;
    int bn = blockIdx.y * BN;
    int tid = threadIdx.x;
    int tm = (tid >> 4) << 3;   // 0..120
    int tn = (tid & 15) << 2;   // 0..60
    float acc[8][4] = {};

    for (int k0 = 0; k0 < KD; k0 += BK) {
        // Load A tile: 512 float4s, transpose into As[kk][m]
        #pragma unroll
        for (int f = tid; f < 512; f += 256) {
            int ml = f >> 2, c = f & 3;
            int gm = bm + ml;
            float4 v = (gm < M) ? *(const float4*)&A[(long)gm * KD + k0 + 4 * c]
                                : make_float4(0.f, 0.f, 0.f, 0.f);
            As[4 * c + 0][ml] = v.x;
            As[4 * c + 1][ml] = v.y;
            As[4 * c + 2][ml] = v.z;
            As[4 * c + 3][ml] = v.w;
        }
        // Load B tile: 256 float4s, 1 per thread, no transpose
        {
            int kk = tid >> 4;
            int nn = (tid & 15) << 2;
            *(float4*)&Bs[kk][nn] = *(const float4*)&B[(long)(k0 + kk) * ND + bn + nn];
        }
        __syncthreads();
        #pragma unroll
        for (int kk = 0; kk < BK; kk++) {
            float4 a0 = *(const float4*)&As[kk][tm];
            float4 a1 = *(const float4*)&As[kk][tm + 4];
            float4 b  = *(const float4*)&Bs[kk][tn];
            acc[0][0] += a0.x * b.x; acc[0][1] += a0.x * b.y; acc[0][2] += a0.x * b.z; acc[0][3] += a0.x * b.w;
            acc[1][0] += a0.y * b.x; acc[1][1] += a0.y * b.y; acc[1][2] += a0.y * b.z; acc[1][3] += a0.y * b.w;
            acc[2][0] += a0.z * b.x; acc[2][1] += a0.z * b.y; acc[2][2] += a0.z * b.z; acc[2][3] += a0.z * b.w;
            acc[3][0] += a0.w * b.x; acc[3][1] += a0.w * b.y; acc[3][2] += a0.w * b.z; acc[3][3] += a0.w * b.w;
            acc[4][0] += a1.x * b.x; acc[4][1] += a1.x * b.y; acc[4][2] += a1.x * b.z; acc[4][3] += a1.x * b.w;
            acc[5][0] += a1.y * b.x; acc[5][1] += a1.y * b.y; acc[5][2] += a1.y * b.z; acc[5][3] += a1.y * b.w;
            acc[6][0] += a1.z * b.x; acc[6][1] += a1.z * b.y; acc[6][2] += a1.z * b.z; acc[6][3] += a1.z * b.w;
            acc[7][0] += a1.w * b.x; acc[7][1] += a1.w * b.y; acc[7][2] += a1.w * b.z; acc[7][3] += a1.w * b.w;
        }
        __syncthreads();
    }
    #pragma unroll
    for (int i = 0; i < 8; i++) {
        int gm = bm + tm + i;
        if (gm < M) {
            float di = g_dinv[gm];
            float4 v = make_float4(di * acc[i][0], di * acc[i][1],
                                   di * acc[i][2], di * acc[i][3]);
            *(float4*)&C[(long)gm * ND + bn + tn] = v;
        }
    }
}

// ---------------- gather aggregation + bias + tanh (F=128, pre-scaled input) ----------------
// h rows are already scaled by dinv[src]; out = tanh(dinv[dst]*(h[dst] + sum h[s]) + b)
__global__ void __launch_bounds__(256) k_agg128(const float* __restrict__ h,
                                                const float* __restrict__ bias,
                                                float* __restrict__ out, int n) {
    int node = blockIdx.x * 8 + (threadIdx.x >> 5);
    if (node >= n) return;
    int lane = threadIdx.x & 31;
    const float4* hv = (const float4*)h;
    float di = g_dinv[node];
    float4 acc = __ldg(&hv[(long)node * 32 + lane]);  // self term: dinv[d]*h[d] = h'[d]
    int beg = g_rowptr[node], end = g_rowptr[node + 1];
    #pragma unroll 4
    for (int p = beg; p < end; p++) {
        int s = g_col[p];
        float4 v = __ldg(&hv[(long)s * 32 + lane]);
        acc.x += v.x; acc.y += v.y; acc.z += v.z; acc.w += v.w;
    }
    float4 b = __ldg(&((const float4*)bias)[lane]);
    float4 r;
    r.x = tanhf(di * acc.x + b.x);
    r.y = tanhf(di * acc.y + b.y);
    r.z = tanhf(di * acc.z + b.z);
    r.w = tanhf(di * acc.w + b.w);
    ((float4*)out)[(long)node * 32 + lane] = r;
}

// ---------------- fused agg(F=64) + MLP head ----------------
// h2 = tanh(dinv*(h[dst]+sum h[s]) + b2); out = tanh(h2@Wf1+bf1)@Wf2+bf2
__global__ void __launch_bounds__(256) k_agg64_mlp(const float* __restrict__ h,
                                                   const float* __restrict__ b2,
                                                   const float* __restrict__ Wf1,
                                                   const float* __restrict__ bf1,
                                                   const float* __restrict__ Wf2,
                                                   const float* __restrict__ bf2,
                                                   float* __restrict__ out, int n) {
    __shared__ float sW[64 * 32];
    __shared__ float sb1[32];
    __shared__ float sW2[32];
    __shared__ float sb2;
    __shared__ float stage[8][64];
    for (int i = threadIdx.x; i < 64 * 32; i += blockDim.x) sW[i] = Wf1[i];
    if (threadIdx.x < 32) { sb1[threadIdx.x] = bf1[threadIdx.x]; sW2[threadIdx.x] = Wf2[threadIdx.x]; }
    if (threadIdx.x == 0) sb2 = bf2[0];
    __syncthreads();

    int w = threadIdx.x >> 5;
    int node = blockIdx.x * 8 + w;
    if (node >= n) return;
    int lane = threadIdx.x & 31;

    // aggregation (features 2*lane, 2*lane+1)
    const float2* hv = (const float2*)h;
    float di = g_dinv[node];
    float2 acc = __ldg(&hv[(long)node * 32 + lane]);  // self term (pre-scaled)
    int beg = g_rowptr[node], end = g_rowptr[node + 1];
    #pragma unroll 4
    for (int p = beg; p < end; p++) {
        int s = g_col[p];
        float2 v = __ldg(&hv[(long)s * 32 + lane]);
        acc.x += v.x; acc.y += v.y;
    }
    float2 bb = __ldg(&((const float2*)b2)[lane]);
    stage[w][2 * lane]     = tanhf(di * acc.x + bb.x);
    stage[w][2 * lane + 1] = tanhf(di * acc.y + bb.y);
    __syncwarp();

    // MLP head from smem stage
    float a1 = sb1[lane];
    #pragma unroll
    for (int j = 0; j < 64; j++)
        a1 += stage[w][j] * sW[j * 32 + lane];
    float t = tanhf(a1);
    float y = t * sW2[lane];
    #pragma unroll
    for (int off = 16; off; off >>= 1)
        y += __shfl_down_sync(0xffffffffu, y, off);
    if (lane == 0) out[node] = y + sb2;
}

// ---------------- launch ----------------
extern "C" void kernel_launch(void* const* d_in, const int* in_sizes, int n_in,
                              void* d_out, int out_size) {
    const float* x   = (const float*)d_in[0];
    const void*  ei  = d_in[1];
    const float* W1  = (const float*)d_in[2];
    const float* b1  = (const float*)d_in[3];
    const float* W2  = (const float*)d_in[4];
    const float* b2  = (const float*)d_in[5];
    const float* Wf1 = (const float*)d_in[6];
    const float* bf1 = (const float*)d_in[7];
    const float* Wf2 = (const float*)d_in[8];
    const float* bf2 = (const float*)d_in[9];
    float* out = (float*)d_out;

    int n = in_sizes[0] / 128;   // 50000
    int e = in_sizes[1] / 2;     // 800000

    float* bufA; cudaGetSymbolAddress((void**)&bufA, g_bufA);
    float* bufB; cudaGetSymbolAddress((void**)&bufB, g_bufB);
    int*   degp; cudaGetSymbolAddress((void**)&degp, g_deg);

    int ge = (e + 255) / 256;
    int gw = (n + 7) / 8;        // warp-per-node kernels

    // CSR build
    k_detect<<<1, 1024>>>(ei, e);
    cudaMemsetAsync(degp, 0, (size_t)n * sizeof(int));
    k_count<<<ge, 256>>>(ei, e);
    k_scan<<<1, 1024>>>(n, e);
    k_fill<<<ge, 256>>>(ei, e);

    // Layer 1: h1' = dinv * tanh-free transform; agg applies tanh
    {
        dim3 grid((n + 127) / 128, 2);
        k_gemm<128, 128><<<grid, 256>>>(x, W1, bufA, n);
    }
    k_agg128<<<gw, 256>>>(bufA, b1, bufB, n);

    // Layer 2 GEMM (scaled) + fused agg64+MLP head
    {
        dim3 grid((n + 127) / 128, 1);
        k_gemm<128, 64><<<grid, 256>>>(bufB, W2, bufA, n);
    }
    k_agg64_mlp<<<gw, 256>>>(bufA, b2, Wf1, bf1, Wf2, bf2, out, n);
}

// round 8
// speedup vs baseline: 1.5353x; 1.1999x over previous
#include <cuda_runtime.h>
#include <cuda_bf16.h>
#include <math.h>

// Problem-fixed capacities
#define NMAX 50000
#define EMAX 800000
#define SCAN_BLK 256
#define SCAN_GRID ((NMAX + SCAN_BLK - 1) / SCAN_BLK)   // 196

// ---------------- scratch (no allocation allowed) ----------------
__device__ int   g_is64;
__device__ int   g_deg[NMAX];
__device__ int   g_cursor[NMAX];
__device__ float g_dinv[NMAX];
__device__ int   g_rowptr[NMAX + 1];
__device__ int   g_col[EMAX];
__device__ int   g_bsum[SCAN_GRID];
__device__ int   g_boff[SCAN_GRID];
__device__ __align__(256) float g_bufA[NMAX * 128];
__device__ __align__(256) float g_bufB[NMAX * 128];

// Edge index accessor: handles int32 (JAX x64-disabled) and int64 layouts.
__device__ __forceinline__ int edge_at(const void* ei, long idx) {
    if (g_is64) return (int)((const long long*)ei)[idx];
    return ((const int*)ei)[idx];
}

// ---------------- dtype detection (parallel) ----------------
__global__ void k_detect(const void* ei, int e) {
    const long long* p = (const long long*)ei;
    int m = e < 2048 ? e : 2048;
    int ok = 1;
    for (int i = threadIdx.x; i < m; i += blockDim.x) {
        long long v = p[i];
        if (v < 0 || v >= NMAX) ok = 0;
    }
    int all = __syncthreads_and(ok);
    if (threadIdx.x == 0) g_is64 = all;
}

// ---------------- degree count (4 edges/thread, vectorized int32 path) ----------------
__global__ void k_count(const void* __restrict__ ei, int e) {
    int i4 = (blockIdx.x * blockDim.x + threadIdx.x) * 4;
    if (i4 >= e) return;
    if (!g_is64 && (e & 3) == 0) {
        const int4* p = (const int4*)((const int*)ei + e);
        int4 d = p[i4 >> 2];
        if (d.x >= 0 && d.x < NMAX) atomicAdd(&g_deg[d.x], 1);
        if (d.y >= 0 && d.y < NMAX) atomicAdd(&g_deg[d.y], 1);
        if (d.z >= 0 && d.z < NMAX) atomicAdd(&g_deg[d.z], 1);
        if (d.w >= 0 && d.w < NMAX) atomicAdd(&g_deg[d.w], 1);
    } else {
        int lim = (i4 + 4 < e) ? i4 + 4 : e;
        for (int i = i4; i < lim; i++) {
            int d = edge_at(ei, (long)e + i);
            if (d >= 0 && d < NMAX) atomicAdd(&g_deg[d], 1);
        }
    }
}

// ---------------- 3-phase parallel scan ----------------
__global__ void k_scan1(int n) {
    __shared__ int wsum[8];
    int blk = blockIdx.x, tid = threadIdx.x;
    int i = blk * SCAN_BLK + tid;
    int lane = tid & 31, wid = tid >> 5;
    int v = (i < n) ? g_deg[i] : 0;
    if (i < n) g_dinv[i] = rsqrtf((float)(v + 1));  // +1 self loop
    int incl = v;
    #pragma unroll
    for (int off = 1; off < 32; off <<= 1) {
        int t = __shfl_up_sync(0xffffffffu, incl, off);
        if (lane >= off) incl += t;
    }
    if (lane == 31) wsum[wid] = incl;
    __syncthreads();
    if (wid == 0 && lane < 8) {
        int ws = wsum[lane];
        int wincl = ws;
        #pragma unroll
        for (int off = 1; off < 8; off <<= 1) {
            int t = __shfl_up_sync(0xffu, wincl, off);
            if (lane >= off) wincl += t;
        }
        wsum[lane] = wincl - ws;  // exclusive warp prefix
        if (lane == 7) g_bsum[blk] = wincl;
    }
    __syncthreads();
    if (i < n) g_rowptr[i] = wsum[wid] + incl - v;  // block-local exclusive
}

__global__ void k_scan2(int nblk) {
    int tid = threadIdx.x, lane = tid & 31, wid = tid >> 5;
    __shared__ int wsum[8];
    int v = (tid < nblk) ? g_bsum[tid] : 0;
    int incl = v;
    #pragma unroll
    for (int off = 1; off < 32; off <<= 1) {
        int t = __shfl_up_sync(0xffffffffu, incl, off);
        if (lane >= off) incl += t;
    }
    if (lane == 31) wsum[wid] = incl;
    __syncthreads();
    if (wid == 0 && lane < 8) {
        int ws = wsum[lane];
        int wincl = ws;
        #pragma unroll
        for (int off = 1; off < 8; off <<= 1) {
            int t = __shfl_up_sync(0xffu, wincl, off);
            if (lane >= off) wincl += t;
        }
        wsum[lane] = wincl - ws;
    }
    __syncthreads();
    if (tid < nblk) g_boff[tid] = wsum[wid] + incl - v;
}

__global__ void k_scan3(int n, int e_total) {
    int i = blockIdx.x * blockDim.x + threadIdx.x;
    if (i < n) {
        int r = g_rowptr[i] + g_boff[blockIdx.x];
        g_rowptr[i] = r;
        g_cursor[i] = r;
    }
    if (i == 0) g_rowptr[n] = e_total;
}

// ---------------- CSR fill (4 edges/thread) ----------------
__global__ void k_fill(const void* __restrict__ ei, int e) {
    int i4 = (blockIdx.x * blockDim.x + threadIdx.x) * 4;
    if (i4 >= e) return;
    if (!g_is64 && (e & 3) == 0) {
        const int4* ps = (const int4*)(const int*)ei;
        const int4* pd = (const int4*)((const int*)ei + e);
        int4 s = ps[i4 >> 2];
        int4 d = pd[i4 >> 2];
        #pragma unroll
        for (int j = 0; j < 4; j++) {
            int ss = j == 0 ? s.x : j == 1 ? s.y : j == 2 ? s.z : s.w;
            int dd = j == 0 ? d.x : j == 1 ? d.y : j == 2 ? d.z : d.w;
            if (ss >= 0 && ss < NMAX && dd >= 0 && dd < NMAX) {
                int pos = atomicAdd(&g_cursor[dd], 1);
                if (pos >= 0 && pos < EMAX) g_col[pos] = ss;
            }
        }
    } else {
        int lim = (i4 + 4 < e) ? i4 + 4 : e;
        for (int i = i4; i < lim; i++) {
            int s = edge_at(ei, i);
            int d = edge_at(ei, (long)e + i);
            if (s >= 0 && s < NMAX && d >= 0 && d < NMAX) {
                int pos = atomicAdd(&g_cursor[d], 1);
                if (pos >= 0 && pos < EMAX) g_col[pos] = s;
            }
        }
    }
}

// ---------------- fp32 GEMM + dinv row-scale: C[m,:] = dinv[m] * (A[m,:] @ B) ----------------
template<int KD, int ND>
__global__ void __launch_bounds__(256) k_gemm(const float* __restrict__ A,
                                              const float* __restrict__ B,
                                              float* __restrict__ C, int M) {
    const int BM = 128, BN = 64, BK = 16;
    __shared__ float As[BK][BM + 4];
    __shared__ float Bs[BK][BN];
    int bm = blockIdx.x * BM;
    int bn = blockIdx.y * BN;
    int tid = threadIdx.x;
    int tm = (tid >> 4) << 3;
    int tn = (tid & 15) << 2;
    float acc[8][4] = {};

    for (int k0 = 0; k0 < KD; k0 += BK) {
        #pragma unroll
        for (int f = tid; f < 512; f += 256) {
            int ml = f >> 2, c = f & 3;
            int gm = bm + ml;
            float4 v = (gm < M) ? *(const float4*)&A[(long)gm * KD + k0 + 4 * c]
                                : make_float4(0.f, 0.f, 0.f, 0.f);
            As[4 * c + 0][ml] = v.x;
            As[4 * c + 1][ml] = v.y;
            As[4 * c + 2][ml] = v.z;
            As[4 * c + 3][ml] = v.w;
        }
        {
            int kk = tid >> 4;
            int nn = (tid & 15) << 2;
            *(float4*)&Bs[kk][nn] = *(const float4*)&B[(long)(k0 + kk) * ND + bn + nn];
        }
        __syncthreads();
        #pragma unroll
        for (int kk = 0; kk < BK; kk++) {
            float4 a0 = *(const float4*)&As[kk][tm];
            float4 a1 = *(const float4*)&As[kk][tm + 4];
            float4 b  = *(const float4*)&Bs[kk][tn];
            acc[0][0] += a0.x * b.x; acc[0][1] += a0.x * b.y; acc[0][2] += a0.x * b.z; acc[0][3] += a0.x * b.w;
            acc[1][0] += a0.y * b.x; acc[1][1] += a0.y * b.y; acc[1][2] += a0.y * b.z; acc[1][3] += a0.y * b.w;
            acc[2][0] += a0.z * b.x; acc[2][1] += a0.z * b.y; acc[2][2] += a0.z * b.z; acc[2][3] += a0.z * b.w;
            acc[3][0] += a0.w * b.x; acc[3][1] += a0.w * b.y; acc[3][2] += a0.w * b.z; acc[3][3] += a0.w * b.w;
            acc[4][0] += a1.x * b.x; acc[4][1] += a1.x * b.y; acc[4][2] += a1.x * b.z; acc[4][3] += a1.x * b.w;
            acc[5][0] += a1.y * b.x; acc[5][1] += a1.y * b.y; acc[5][2] += a1.y * b.z; acc[5][3] += a1.y * b.w;
            acc[6][0] += a1.z * b.x; acc[6][1] += a1.z * b.y; acc[6][2] += a1.z * b.z; acc[6][3] += a1.z * b.w;
            acc[7][0] += a1.w * b.x; acc[7][1] += a1.w * b.y; acc[7][2] += a1.w * b.z; acc[7][3] += a1.w * b.w;
        }
        __syncthreads();
    }
    #pragma unroll
    for (int i = 0; i < 8; i++) {
        int gm = bm + tm + i;
        if (gm < M) {
            float di = g_dinv[gm];
            float4 v = make_float4(di * acc[i][0], di * acc[i][1],
                                   di * acc[i][2], di * acc[i][3]);
            *(float4*)&C[(long)gm * ND + bn + tn] = v;
        }
    }
}

// ---------------- gather aggregation + bias + tanh (F=128, pre-scaled input) ----------------
__global__ void __launch_bounds__(256) k_agg128(const float* __restrict__ h,
                                                const float* __restrict__ bias,
                                                float* __restrict__ out, int n) {
    int node = blockIdx.x * 8 + (threadIdx.x >> 5);
    if (node >= n) return;
    int lane = threadIdx.x & 31;
    const float4* hv = (const float4*)h;
    float di = g_dinv[node];
    float4 acc = __ldg(&hv[(long)node * 32 + lane]);  // self term (pre-scaled)
    int beg = g_rowptr[node], end = g_rowptr[node + 1];
    #pragma unroll 4
    for (int p = beg; p < end; p++) {
        int s = g_col[p];
        float4 v = __ldg(&hv[(long)s * 32 + lane]);
        acc.x += v.x; acc.y += v.y; acc.z += v.z; acc.w += v.w;
    }
    float4 b = __ldg(&((const float4*)bias)[lane]);
    float4 r;
    r.x = tanhf(di * acc.x + b.x);
    r.y = tanhf(di * acc.y + b.y);
    r.z = tanhf(di * acc.z + b.z);
    r.w = tanhf(di * acc.w + b.w);
    ((float4*)out)[(long)node * 32 + lane] = r;
}

// ---------------- fused agg(F=64) + MLP head ----------------
__global__ void __launch_bounds__(256) k_agg64_mlp(const float* __restrict__ h,
                                                   const float* __restrict__ b2,
                                                   const float* __restrict__ Wf1,
                                                   const float* __restrict__ bf1,
                                                   const float* __restrict__ Wf2,
                                                   const float* __restrict__ bf2,
                                                   float* __restrict__ out, int n) {
    __shared__ float sW[64 * 32];
    __shared__ float sb1[32];
    __shared__ float sW2[32];
    __shared__ float sb2;
    __shared__ float stage[8][64];
    for (int i = threadIdx.x; i < 64 * 32; i += blockDim.x) sW[i] = Wf1[i];
    if (threadIdx.x < 32) { sb1[threadIdx.x] = bf1[threadIdx.x]; sW2[threadIdx.x] = Wf2[threadIdx.x]; }
    if (threadIdx.x == 0) sb2 = bf2[0];
    __syncthreads();

    int w = threadIdx.x >> 5;
    int node = blockIdx.x * 8 + w;
    if (node >= n) return;
    int lane = threadIdx.x & 31;

    const float2* hv = (const float2*)h;
    float di = g_dinv[node];
    float2 acc = __ldg(&hv[(long)node * 32 + lane]);
    int beg = g_rowptr[node], end = g_rowptr[node + 1];
    #pragma unroll 4
    for (int p = beg; p < end; p++) {
        int s = g_col[p];
        float2 v = __ldg(&hv[(long)s * 32 + lane]);
        acc.x += v.x; acc.y += v.y;
    }
    float2 bb = __ldg(&((const float2*)b2)[lane]);
    stage[w][2 * lane]     = tanhf(di * acc.x + bb.x);
    stage[w][2 * lane + 1] = tanhf(di * acc.y + bb.y);
    __syncwarp();

    float a1 = sb1[lane];
    #pragma unroll
    for (int j = 0; j < 64; j++)
        a1 += stage[w][j] * sW[j * 32 + lane];
    float t = tanhf(a1);
    float y = t * sW2[lane];
    #pragma unroll
    for (int off = 16; off; off >>= 1)
        y += __shfl_down_sync(0xffffffffu, y, off);
    if (lane == 0) out[node] = y + sb2;
}

// ---------------- launch ----------------
extern "C" void kernel_launch(void* const* d_in, const int* in_sizes, int n_in,
                              void* d_out, int out_size) {
    const float* x   = (const float*)d_in[0];
    const void*  ei  = d_in[1];
    const float* W1  = (const float*)d_in[2];
    const float* b1  = (const float*)d_in[3];
    const float* W2  = (const float*)d_in[4];
    const float* b2  = (const float*)d_in[5];
    const float* Wf1 = (const float*)d_in[6];
    const float* bf1 = (const float*)d_in[7];
    const float* Wf2 = (const float*)d_in[8];
    const float* bf2 = (const float*)d_in[9];
    float* out = (float*)d_out;

    int n = in_sizes[0] / 128;   // 50000
    int e = in_sizes[1] / 2;     // 800000

    float* bufA; cudaGetSymbolAddress((void**)&bufA, g_bufA);
    float* bufB; cudaGetSymbolAddress((void**)&bufB, g_bufB);
    int*   degp; cudaGetSymbolAddress((void**)&degp, g_deg);

    // One-time host-object setup (no device memory; identical launches every call)
    static cudaStream_t sB = nullptr;
    static cudaEvent_t evFork = nullptr, evJoin = nullptr;
    if (!sB) {
        cudaStreamCreateWithFlags(&sB, cudaStreamNonBlocking);
        cudaEventCreateWithFlags(&evFork, cudaEventDisableTiming);
        cudaEventCreateWithFlags(&evJoin, cudaEventDisableTiming);
    }

    int ge4 = (e + 1023) / 1024;   // 4 edges per thread, 256 threads
    int gw  = (n + 7) / 8;

    // Fork: CSR build on sB, concurrent with GEMM1 on the main stream
    cudaEventRecord(evFork, 0);
    cudaStreamWaitEvent(sB, evFork, 0);

    k_detect<<<1, 1024, 0, sB>>>(ei, e);
    cudaMemsetAsync(degp, 0, (size_t)n * sizeof(int), sB);
    k_count<<<ge4, 256, 0, sB>>>(ei, e);
    k_scan1<<<SCAN_GRID, SCAN_BLK, 0, sB>>>(n);
    k_scan2<<<1, 256, 0, sB>>>(SCAN_GRID);
    k_scan3<<<SCAN_GRID, SCAN_BLK, 0, sB>>>(n, e);
    k_fill<<<ge4, 256, 0, sB>>>(ei, e);
    cudaEventRecord(evJoin, sB);

    // GEMM1 on main stream (independent of the graph).
    // NOTE: epilogue reads g_dinv, which IS graph-dependent -> move scale to agg input?
    // No: k_gemm epilogue scales by dinv, so it must wait for scan. Instead, GEMM1
    // writes unscaled and agg applies dinv[s] per gather? That reintroduces g_w.
    // Resolution: GEMM1 runs unscaled is wrong; keep dependency correct by having
    // GEMM wait only on dinv (scan), not fill. Simpler & correct: join before GEMM epilogue
    // is impossible per-kernel, so wait for evJoin before GEMM1? That kills overlap.
    // Correct fix: GEMM1 scales with dinv -> needs scan but NOT fill. Fill is the long pole
    // anyway. So: record event after scan3 and let main stream wait on that.
    // (Implemented below via evScan.)
    static cudaEvent_t evScan = nullptr;
    if (!evScan) cudaEventCreateWithFlags(&evScan, cudaEventDisableTiming);
    // re-issue: evScan after scan3 — but scan3 already launched above; event record now
    // still captures dependency on all prior sB work including scan3 (and detect/count),
    // but NOT on k_fill? Events record stream position; we must record before k_fill.
    // To keep ordering right we instead record evScan immediately after k_scan3 next time.
    // For this round, simply order: record here covers fill too — lost overlap on GEMM1
    // epilogue only. Acceptable: GEMM main loop still overlaps count+scan.
    cudaStreamWaitEvent(0, evJoin, 0);

    {
        dim3 grid((n + 127) / 128, 2);
        k_gemm<128, 128><<<grid, 256>>>(x, W1, bufA, n);
    }
    k_agg128<<<gw, 256>>>(bufA, b1, bufB, n);

    {
        dim3 grid((n + 127) / 128, 1);
        k_gemm<128, 64><<<grid, 256>>>(bufB, W2, bufA, n);
    }
    k_agg64_mlp<<<gw, 256>>>(bufA, b2, Wf1, bf1, Wf2, bf2, out, n);
}

// round 9
// speedup vs baseline: 1.5541x; 1.0123x over previous
#include <cuda_runtime.h>
#include <cuda_bf16.h>
#include <math.h>

// Problem-fixed capacities
#define NMAX 50000
#define EMAX 800000
#define SCAN_BLK 256
#define SCAN_GRID ((NMAX + SCAN_BLK - 1) / SCAN_BLK)   // 196

// ---------------- scratch (no allocation allowed) ----------------
__device__ int   g_is64;
__device__ int   g_deg[NMAX];
__device__ int   g_cursor[NMAX];
__device__ float g_dinv[NMAX];
__device__ int   g_rowptr[NMAX + 1];
__device__ int   g_col[EMAX];
__device__ float g_w[EMAX];                 // dinv[src] per CSR slot (layer-1 agg)
__device__ int   g_bsum[SCAN_GRID];
__device__ int   g_boff[SCAN_GRID];
__device__ __align__(256) float g_bufA[NMAX * 128];
__device__ __align__(256) float g_bufB[NMAX * 128];

// Edge index accessor: handles int32 (JAX x64-disabled) and int64 layouts.
__device__ __forceinline__ int edge_at(const void* ei, long idx) {
    if (g_is64) return (int)((const long long*)ei)[idx];
    return ((const int*)ei)[idx];
}

// ---------------- dtype detection (parallel) ----------------
__global__ void k_detect(const void* ei, int e) {
    const long long* p = (const long long*)ei;
    int m = e < 2048 ? e : 2048;
    int ok = 1;
    for (int i = threadIdx.x; i < m; i += blockDim.x) {
        long long v = p[i];
        if (v < 0 || v >= NMAX) ok = 0;
    }
    int all = __syncthreads_and(ok);
    if (threadIdx.x == 0) g_is64 = all;
}

// ---------------- degree count (4 edges/thread, vectorized int32 path) ----------------
__global__ void k_count(const void* __restrict__ ei, int e) {
    int i4 = (blockIdx.x * blockDim.x + threadIdx.x) * 4;
    if (i4 >= e) return;
    if (!g_is64 && (e & 3) == 0) {
        const int4* p = (const int4*)((const int*)ei + e);
        int4 d = p[i4 >> 2];
        if (d.x >= 0 && d.x < NMAX) atomicAdd(&g_deg[d.x], 1);
        if (d.y >= 0 && d.y < NMAX) atomicAdd(&g_deg[d.y], 1);
        if (d.z >= 0 && d.z < NMAX) atomicAdd(&g_deg[d.z], 1);
        if (d.w >= 0 && d.w < NMAX) atomicAdd(&g_deg[d.w], 1);
    } else {
        int lim = (i4 + 4 < e) ? i4 + 4 : e;
        for (int i = i4; i < lim; i++) {
            int d = edge_at(ei, (long)e + i);
            if (d >= 0 && d < NMAX) atomicAdd(&g_deg[d], 1);
        }
    }
}

// ---------------- 3-phase parallel scan ----------------
__global__ void k_scan1(int n) {
    __shared__ int wsum[8];
    int blk = blockIdx.x, tid = threadIdx.x;
    int i = blk * SCAN_BLK + tid;
    int lane = tid & 31, wid = tid >> 5;
    int v = (i < n) ? g_deg[i] : 0;
    if (i < n) g_dinv[i] = rsqrtf((float)(v + 1));  // +1 self loop
    int incl = v;
    #pragma unroll
    for (int off = 1; off < 32; off <<= 1) {
        int t = __shfl_up_sync(0xffffffffu, incl, off);
        if (lane >= off) incl += t;
    }
    if (lane == 31) wsum[wid] = incl;
    __syncthreads();
    if (wid == 0 && lane < 8) {
        int ws = wsum[lane];
        int wincl = ws;
        #pragma unroll
        for (int off = 1; off < 8; off <<= 1) {
            int t = __shfl_up_sync(0xffu, wincl, off);
            if (lane >= off) wincl += t;
        }
        wsum[lane] = wincl - ws;  // exclusive warp prefix
        if (lane == 7) g_bsum[blk] = wincl;
    }
    __syncthreads();
    if (i < n) g_rowptr[i] = wsum[wid] + incl - v;  // block-local exclusive
}

__global__ void k_scan2(int nblk) {
    int tid = threadIdx.x, lane = tid & 31, wid = tid >> 5;
    __shared__ int wsum[8];
    int v = (tid < nblk) ? g_bsum[tid] : 0;
    int incl = v;
    #pragma unroll
    for (int off = 1; off < 32; off <<= 1) {
        int t = __shfl_up_sync(0xffffffffu, incl, off);
        if (lane >= off) incl += t;
    }
    if (lane == 31) wsum[wid] = incl;
    __syncthreads();
    if (wid == 0 && lane < 8) {
        int ws = wsum[lane];
        int wincl = ws;
        #pragma unroll
        for (int off = 1; off < 8; off <<= 1) {
            int t = __shfl_up_sync(0xffu, wincl, off);
            if (lane >= off) wincl += t;
        }
        wsum[lane] = wincl - ws;
    }
    __syncthreads();
    if (tid < nblk) g_boff[tid] = wsum[wid] + incl - v;
}

__global__ void k_scan3(int n, int e_total) {
    int i = blockIdx.x * blockDim.x + threadIdx.x;
    if (i < n) {
        int r = g_rowptr[i] + g_boff[blockIdx.x];
        g_rowptr[i] = r;
        g_cursor[i] = r;
    }
    if (i == 0) g_rowptr[n] = e_total;
}

// ---------------- CSR fill (4 edges/thread; writes col + w=dinv[src]) ----------------
__global__ void k_fill(const void* __restrict__ ei, int e) {
    int i4 = (blockIdx.x * blockDim.x + threadIdx.x) * 4;
    if (i4 >= e) return;
    if (!g_is64 && (e & 3) == 0) {
        const int4* ps = (const int4*)(const int*)ei;
        const int4* pd = (const int4*)((const int*)ei + e);
        int4 s = ps[i4 >> 2];
        int4 d = pd[i4 >> 2];
        #pragma unroll
        for (int j = 0; j < 4; j++) {
            int ss = j == 0 ? s.x : j == 1 ? s.y : j == 2 ? s.z : s.w;
            int dd = j == 0 ? d.x : j == 1 ? d.y : j == 2 ? d.z : d.w;
            if (ss >= 0 && ss < NMAX && dd >= 0 && dd < NMAX) {
                int pos = atomicAdd(&g_cursor[dd], 1);
                if (pos >= 0 && pos < EMAX) { g_col[pos] = ss; g_w[pos] = g_dinv[ss]; }
            }
        }
    } else {
        int lim = (i4 + 4 < e) ? i4 + 4 : e;
        for (int i = i4; i < lim; i++) {
            int s = edge_at(ei, i);
            int d = edge_at(ei, (long)e + i);
            if (s >= 0 && s < NMAX && d >= 0 && d < NMAX) {
                int pos = atomicAdd(&g_cursor[d], 1);
                if (pos >= 0 && pos < EMAX) { g_col[pos] = s; g_w[pos] = g_dinv[s]; }
            }
        }
    }
}

// ---------------- fp32 GEMM: C = A @ B, optional dinv row-scale ----------------
// 128x64 CTA tile, BK=16, 8x4 per-thread, all-LDS.128 inner loop.
template<int KD, int ND, bool SCALE>
__global__ void __launch_bounds__(256) k_gemm(const float* __restrict__ A,
                                              const float* __restrict__ B,
                                              float* __restrict__ C, int M) {
    const int BM = 128, BN = 64, BK = 16;
    __shared__ float As[BK][BM + 4];
    __shared__ float Bs[BK][BN];
    int bm = blockIdx.x * BM;
    int bn = blockIdx.y * BN;
    int tid = threadIdx.x;
    int tm = (tid >> 4) << 3;
    int tn = (tid & 15) << 2;
    float acc[8][4] = {};

    for (int k0 = 0; k0 < KD; k0 += BK) {
        #pragma unroll
        for (int f = tid; f < 512; f += 256) {
            int ml = f >> 2, c = f & 3;
            int gm = bm + ml;
            float4 v = (gm < M) ? *(const float4*)&A[(long)gm * KD + k0 + 4 * c]
                                : make_float4(0.f, 0.f, 0.f, 0.f);
            As[4 * c + 0][ml] = v.x;
            As[4 * c + 1][ml] = v.y;
            As[4 * c + 2][ml] = v.z;
            As[4 * c + 3][ml] = v.w;
        }
        {
            int kk = tid >> 4;
            int nn = (tid & 15) << 2;
            *(float4*)&Bs[kk][nn] = *(const float4*)&B[(long)(k0 + kk) * ND + bn + nn];
        }
        __syncthreads();
        #pragma unroll
        for (int kk = 0; kk < BK; kk++) {
            float4 a0 = *(const float4*)&As[kk][tm];
            float4 a1 = *(const float4*)&As[kk][tm + 4];
            float4 b  = *(const float4*)&Bs[kk][tn];
            acc[0][0] += a0.x * b.x; acc[0][1] += a0.x * b.y; acc[0][2] += a0.x * b.z; acc[0][3] += a0.x * b.w;
            acc[1][0] += a0.y * b.x; acc[1][1] += a0.y * b.y; acc[1][2] += a0.y * b.z; acc[1][3] += a0.y * b.w;
            acc[2][0] += a0.z * b.x; acc[2][1] += a0.z * b.y; acc[2][2] += a0.z * b.z; acc[2][3] += a0.z * b.w;
            acc[3][0] += a0.w * b.x; acc[3][1] += a0.w * b.y; acc[3][2] += a0.w * b.z; acc[3][3] += a0.w * b.w;
            acc[4][0] += a1.x * b.x; acc[4][1] += a1.x * b.y; acc[4][2] += a1.x * b.z; acc[4][3] += a1.x * b.w;
            acc[5][0] += a1.y * b.x; acc[5][1] += a1.y * b.y; acc[5][2] += a1.y * b.z; acc[5][3] += a1.y * b.w;
            acc[6][0] += a1.z * b.x; acc[6][1] += a1.z * b.y; acc[6][2] += a1.z * b.z; acc[6][3] += a1.z * b.w;
            acc[7][0] += a1.w * b.x; acc[7][1] += a1.w * b.y; acc[7][2] += a1.w * b.z; acc[7][3] += a1.w * b.w;
        }
        __syncthreads();
    }
    #pragma unroll
    for (int i = 0; i < 8; i++) {
        int gm = bm + tm + i;
        if (gm < M) {
            float di = SCALE ? g_dinv[gm] : 1.0f;
            float4 v = make_float4(di * acc[i][0], di * acc[i][1],
                                   di * acc[i][2], di * acc[i][3]);
            *(float4*)&C[(long)gm * ND + bn + tn] = v;
        }
    }
}

// ---------------- layer-1 aggregation (F=128, UNscaled input, per-edge weights) ----------------
// out = tanh(dinv_d * (sum w_p*H[s] + dinv_d*H[d]) + b)
__global__ void __launch_bounds__(256) k_agg128(const float* __restrict__ h,
                                                const float* __restrict__ bias,
                                                float* __restrict__ out, int n) {
    int node = blockIdx.x * 8 + (threadIdx.x >> 5);
    if (node >= n) return;
    int lane = threadIdx.x & 31;
    const float4* hv = (const float4*)h;
    float di = g_dinv[node];
    float4 a = __ldg(&hv[(long)node * 32 + lane]);
    float4 acc;
    acc.x = di * a.x; acc.y = di * a.y; acc.z = di * a.z; acc.w = di * a.w;  // self: dinv_d*H[d]
    int beg = g_rowptr[node], end = g_rowptr[node + 1];
    #pragma unroll 4
    for (int p = beg; p < end; p++) {
        int s = g_col[p];
        float ws = g_w[p];
        float4 v = __ldg(&hv[(long)s * 32 + lane]);
        acc.x += ws * v.x; acc.y += ws * v.y; acc.z += ws * v.z; acc.w += ws * v.w;
    }
    float4 b = __ldg(&((const float4*)bias)[lane]);
    float4 r;
    r.x = tanhf(di * acc.x + b.x);
    r.y = tanhf(di * acc.y + b.y);
    r.z = tanhf(di * acc.z + b.z);
    r.w = tanhf(di * acc.w + b.w);
    ((float4*)out)[(long)node * 32 + lane] = r;
}

// ---------------- fused agg(F=64, pre-scaled input) + MLP head ----------------
__global__ void __launch_bounds__(256) k_agg64_mlp(const float* __restrict__ h,
                                                   const float* __restrict__ b2,
                                                   const float* __restrict__ Wf1,
                                                   const float* __restrict__ bf1,
                                                   const float* __restrict__ Wf2,
                                                   const float* __restrict__ bf2,
                                                   float* __restrict__ out, int n) {
    __shared__ float sW[64 * 32];
    __shared__ float sb1[32];
    __shared__ float sW2[32];
    __shared__ float sb2;
    __shared__ float stage[8][64];
    for (int i = threadIdx.x; i < 64 * 32; i += blockDim.x) sW[i] = Wf1[i];
    if (threadIdx.x < 32) { sb1[threadIdx.x] = bf1[threadIdx.x]; sW2[threadIdx.x] = Wf2[threadIdx.x]; }
    if (threadIdx.x == 0) sb2 = bf2[0];
    __syncthreads();

    int w = threadIdx.x >> 5;
    int node = blockIdx.x * 8 + w;
    if (node >= n) return;
    int lane = threadIdx.x & 31;

    const float2* hv = (const float2*)h;
    float di = g_dinv[node];
    float2 acc = __ldg(&hv[(long)node * 32 + lane]);   // self term (pre-scaled rows)
    int beg = g_rowptr[node], end = g_rowptr[node + 1];
    #pragma unroll 4
    for (int p = beg; p < end; p++) {
        int s = g_col[p];
        float2 v = __ldg(&hv[(long)s * 32 + lane]);
        acc.x += v.x; acc.y += v.y;
    }
    float2 bb = __ldg(&((const float2*)b2)[lane]);
    stage[w][2 * lane]     = tanhf(di * acc.x + bb.x);
    stage[w][2 * lane + 1] = tanhf(di * acc.y + bb.y);
    __syncwarp();

    float a1 = sb1[lane];
    #pragma unroll
    for (int j = 0; j < 64; j++)
        a1 += stage[w][j] * sW[j * 32 + lane];
    float t = tanhf(a1);
    float y = t * sW2[lane];
    #pragma unroll
    for (int off = 16; off; off >>= 1)
        y += __shfl_down_sync(0xffffffffu, y, off);
    if (lane == 0) out[node] = y + sb2;
}

// ---------------- launch ----------------
extern "C" void kernel_launch(void* const* d_in, const int* in_sizes, int n_in,
                              void* d_out, int out_size) {
    const float* x   = (const float*)d_in[0];
    const void*  ei  = d_in[1];
    const float* W1  = (const float*)d_in[2];
    const float* b1  = (const float*)d_in[3];
    const float* W2  = (const float*)d_in[4];
    const float* b2  = (const float*)d_in[5];
    const float* Wf1 = (const float*)d_in[6];
    const float* bf1 = (const float*)d_in[7];
    const float* Wf2 = (const float*)d_in[8];
    const float* bf2 = (const float*)d_in[9];
    float* out = (float*)d_out;

    int n = in_sizes[0] / 128;   // 50000
    int e = in_sizes[1] / 2;     // 800000

    float* bufA; cudaGetSymbolAddress((void**)&bufA, g_bufA);
    float* bufB; cudaGetSymbolAddress((void**)&bufB, g_bufB);
    int*   degp; cudaGetSymbolAddress((void**)&degp, g_deg);

    // One-time host-object setup (no device memory; identical launches every call)
    static cudaStream_t sB = nullptr;
    static cudaEvent_t evFork = nullptr, evJoin = nullptr;
    if (!sB) {
        cudaStreamCreateWithFlags(&sB, cudaStreamNonBlocking);
        cudaEventCreateWithFlags(&evFork, cudaEventDisableTiming);
        cudaEventCreateWithFlags(&evJoin, cudaEventDisableTiming);
    }

    int ge4 = (e + 1023) / 1024;   // 4 edges per thread, 256 threads
    int gw  = (n + 7) / 8;

    // Fork: CSR build on sB runs concurrently with GEMM1 (graph-independent) on main.
    cudaEventRecord(evFork, 0);
    cudaStreamWaitEvent(sB, evFork, 0);

    k_detect<<<1, 1024, 0, sB>>>(ei, e);
    cudaMemsetAsync(degp, 0, (size_t)n * sizeof(int), sB);
    k_count<<<ge4, 256, 0, sB>>>(ei, e);
    k_scan1<<<SCAN_GRID, SCAN_BLK, 0, sB>>>(n);
    k_scan2<<<1, 256, 0, sB>>>(SCAN_GRID);
    k_scan3<<<SCAN_GRID, SCAN_BLK, 0, sB>>>(n, e);
    k_fill<<<ge4, 256, 0, sB>>>(ei, e);
    cudaEventRecord(evJoin, sB);

    // GEMM1 (unscaled, fully independent of the graph)
    {
        dim3 grid((n + 127) / 128, 2);
        k_gemm<128, 128, false><<<grid, 256>>>(x, W1, bufA, n);
    }

    // Join: aggregation needs CSR + dinv
    cudaStreamWaitEvent(0, evJoin, 0);
    k_agg128<<<gw, 256>>>(bufA, b1, bufB, n);

    // Layer 2 GEMM (dinv-scaled) + fused agg64+MLP head
    {
        dim3 grid((n + 127) / 128, 1);
        k_gemm<128, 64, true><<<grid, 256>>>(bufB, W2, bufA, n);
    }
    k_agg64_mlp<<<gw, 256>>>(bufA, b2, Wf1, bf1, Wf2, bf2, out, n);
}